// round 15
// baseline (speedup 1.0000x reference)
#include <cuda_runtime.h>
#include <cuda_fp16.h>
#include <cstdint>

#define TM     288
#define KC     64
#define NCHUNK 11
#define EC     128
#define NF     656
#define NTHR   512

// smem byte offsets
#define OFF_A     0           // 2 x 36864 (fp16 A tiles, 288x64 each)
#define OFF_B     73728       // 2 x 16384 (fp16 B tiles)
#define OFF_DIST  106496      // 288*41*4 = 47232
#define OFF_SMUL  153728      // 1152
#define OFF_DPOS  154880      // 1152
#define OFF_GAM   156032      // 512
#define OFF_BET   156544      // 512
#define SMEM_TOTAL 157056
// epilogue reuse of A region:
#define OFF_PSUM  0           // 288*8 float2 = 18432
#define OFF_RMS   20480       // 288 float2 = 2304

// Prepacked W: fp16, [chunk][n][kk] K-major rows of 128B, SW128-swizzled
__device__ __align__(128) __half g_B[NCHUNK * KC * EC];

__device__ __forceinline__ uint32_t smem_u32(const void* p) {
    return (uint32_t)__cvta_generic_to_shared(p);
}
__device__ __forceinline__ void cp_async16(uint32_t dst, const void* src) {
    asm volatile("cp.async.cg.shared.global [%0], [%1], 16;"
                 :: "r"(dst), "l"(src) : "memory");
}
__device__ __forceinline__ void ldsm4(uint32_t& r0, uint32_t& r1,
                                      uint32_t& r2, uint32_t& r3, uint32_t addr) {
    asm volatile("ldmatrix.sync.aligned.m8n8.x4.shared.b16 {%0,%1,%2,%3}, [%4];"
                 : "=r"(r0), "=r"(r1), "=r"(r2), "=r"(r3) : "r"(addr));
}
__device__ __forceinline__ void mma16816(float* d, const uint32_t* a, const uint32_t* b) {
    asm volatile("mma.sync.aligned.m16n8k16.row.col.f32.f16.f16.f32 "
        "{%0,%1,%2,%3}, {%4,%5,%6,%7}, {%8,%9}, {%0,%1,%2,%3};"
        : "+f"(d[0]), "+f"(d[1]), "+f"(d[2]), "+f"(d[3])
        : "r"(a[0]), "r"(a[1]), "r"(a[2]), "r"(a[3]), "r"(b[0]), "r"(b[1]));
}
__device__ __forceinline__ uint32_t sw128(uint32_t off) {
    return off ^ ((off >> 3) & 0x70);
}

// ---- prepack: W_edge -> fp16, swizzled, chunk-contiguous -----------------
__global__ void prepack_kernel(const float* __restrict__ W_edge) {
    int idx = blockIdx.x * 256 + threadIdx.x;
    if (idx >= NCHUNK * KC * EC) return;
    int c   = idx / (KC * EC);
    int rem = idx % (KC * EC);
    int kk  = rem / EC;
    int n   = rem % EC;
    int k   = c * KC + kk;
    float v = (k < NF) ? W_edge[(size_t)k * EC + n] : 0.0f;
    uint32_t off = sw128((uint32_t)(n * 128 + kk * 2));
    *(__half*)((char*)g_B + (size_t)c * 16384 + off) = __float2half(v);
}

// ---- main kernel --------------------------------------------------------
__global__ __launch_bounds__(NTHR, 1)
void spf_kernel(const float* __restrict__ X,
                const int*   __restrict__ residue_idx,
                const int*   __restrict__ chain_labels,
                const int*   __restrict__ E_idx,
                const float* __restrict__ W_pos,
                const float* __restrict__ b_pos,
                const float* __restrict__ ln_gamma,
                const float* __restrict__ ln_beta,
                float*       __restrict__ out,
                int Kn, int A, int nrows, int write_eidx)
{
    extern __shared__ char smem[];
    const uint32_t sb = smem_u32(smem);
    float* dist  = (float*)(smem + OFF_DIST);
    float* smul  = (float*)(smem + OFF_SMUL);
    int*   dposs = (int*)  (smem + OFF_DPOS);
    float* sgam  = (float*)(smem + OFF_GAM);
    float* sbet  = (float*)(smem + OFF_BET);

    const int tid  = threadIdx.x;
    const int wid  = tid >> 5;
    const int lid  = tid & 31;
    const int row0 = blockIdx.x * TM;

    // staging helpers ------------------------------------------------------
    auto stage_B = [&](int c, int b) {
        const char* src = (const char*)g_B + (size_t)c * 16384;
        const uint32_t d = sb + OFF_B + b * 16384;
        #pragma unroll
        for (int i = 0; i < 2; i++) {
            int g = tid + i * NTHR;          // 0..1023
            cp_async16(d + g*16, src + g*16);
        }
        asm volatile("cp.async.commit_group;" ::: "memory");
    };

    auto stage_A = [&](int c, int b) {
        char* ab = smem + OFF_A + b * 36864;
        #pragma unroll
        for (int it = 0; it < 3; it++) {
            const int id = tid + it * NTHR;
            if (id >= 4 * TM) break;
            const int r    = id % TM;
            const int gsub = id / TM;        // 0..3
            const int gl   = c * 4 + gsub;   // global 16-k group
            float vals[16];
            if (gl == 0) {
                const int dp = dposs[r];
                #pragma unroll
                for (int m = 0; m < 16; m++)
                    vals[m] = W_pos[dp*16 + m] + b_pos[m];
            } else if (gl <= 40) {
                const float d  = dist[r*41 + (gl - 1)];
                const float sm = smul[r];
                #pragma unroll
                for (int m = 0; m < 16; m++) {
                    float mu = 2.0f + (float)m * (20.0f / 15.0f);
                    float t  = (d - mu) * 0.8f;
                    vals[m]  = sm * __expf(-t * t);
                }
            } else {
                #pragma unroll
                for (int m = 0; m < 16; m++) vals[m] = 0.0f;
            }
            uint32_t hp[8];
            #pragma unroll
            for (int i = 0; i < 8; i++) {
                __half2 h2 = __floats2half2_rn(vals[2*i], vals[2*i+1]);
                hp[i] = *(uint32_t*)&h2;
            }
            uint32_t base = (uint32_t)(r * 128 + gsub * 32);
            uint32_t s0 = sw128(base), s1 = sw128(base + 16);
            *(uint4*)(ab + s0) = make_uint4(hp[0], hp[1], hp[2], hp[3]);
            *(uint4*)(ab + s1) = make_uint4(hp[4], hp[5], hp[6], hp[7]);
        }
    };

    // kick B chunk-0 staging immediately (independent of phase 1)
    stage_B(0, 0);

    // ---------------- Phase 1: distances, smul, dpos, gamma/beta ----------
    for (int task = tid; task < 2 * TM; task += NTHR) {
        const int r    = task >> 1;
        const int half = task & 1;           // bb atoms {0,1} or {2,3}
        const int row  = row0 + r;
        if (row < nrows) {
            const int i = row / Kn;
            const int j = E_idx[row];
            const int bbm[4] = {1, 0, 2, 3};
            const float* sx = X + ((size_t)j * A + 4) * 3;
            float s[30];
            #pragma unroll
            for (int q = 0; q < 30; q++) s[q] = sx[q];
            #pragma unroll
            for (int aa = 0; aa < 2; aa++) {
                const int a1 = half*2 + aa;
                const float* bx = X + ((size_t)i * A + bbm[a1]) * 3;
                const float b0 = bx[0], b1 = bx[1], b2 = bx[2];
                #pragma unroll
                for (int a2 = 0; a2 < 10; a2++) {
                    float dx = b0 - s[a2*3+0];
                    float dy = b1 - s[a2*3+1];
                    float dz = b2 - s[a2*3+2];
                    dist[r*41 + a1*10 + a2] = sqrtf(dx*dx + dy*dy + dz*dz + 1e-6f);
                }
            }
            if (half == 0) {
                smul[r] = (j == i) ? 0.0f : 1.0f;
                int off  = residue_idx[i] - residue_idx[j];
                int same = (chain_labels[i] == chain_labels[j]);
                dposs[r] = same ? min(max(off + 32, 0), 64) : 65;
                if (write_eidx)
                    out[(size_t)nrows * EC + row] = (float)j;
            }
        } else {
            #pragma unroll
            for (int aa = 0; aa < 2; aa++)
                #pragma unroll
                for (int a2 = 0; a2 < 10; a2++)
                    dist[r*41 + (half*2+aa)*10 + a2] = 0.0f;
            if (half == 0) { smul[r] = 0.0f; dposs[r] = 0; }
        }
    }
    if (tid < 128)      sgam[tid]       = ln_gamma[tid];
    else if (tid < 256) sbet[tid - 128] = ln_beta[tid - 128];
    __syncthreads();

    // prologue: features for chunk 0
    stage_A(0, 0);
    asm volatile("cp.async.wait_group 0;" ::: "memory");
    __syncthreads();

    // ---------------- Phase 2: MMA mainloop (single-pass fp16) ------------
    // 16 warps: 2 M-groups (144 rows = 9 m16) x 8 N-groups (16 cols)
    const int Mg = wid & 1;
    const int Ng = wid >> 1;
    const int q  = lid >> 3;
    const int lr = lid & 7;
    const int axor  = lr << 4;
    const int arow0 = (Mg*144 + lr + (q & 1) * 8) * 128;   // + t*2048 per m16
    const int brow0 = (Ng*16  + lr + (q >> 1) * 8) * 128;
    const int akq = (q >> 1) * 16;
    const int bkq = (q & 1) * 16;

    float acc[9][2][4];
    #pragma unroll
    for (int t = 0; t < 9; t++)
        #pragma unroll
        for (int j = 0; j < 2; j++)
            #pragma unroll
            for (int e = 0; e < 4; e++) acc[t][j][e] = 0.0f;

    for (int c = 0; c < NCHUNK; c++) {
        const int b = c & 1;
        // issue next-chunk B loads first so global latency hides under MMA
        if (c + 1 < NCHUNK) stage_B(c + 1, b ^ 1);

        const uint32_t aB = sb + OFF_A + b * 36864;
        const uint32_t bB = sb + OFF_B + b * 16384;

        #pragma unroll
        for (int ks = 0; ks < 4; ks++) {
            const int kb = ks * 32;
            const uint32_t boff = (uint32_t)(brow0 + ((kb + bkq) ^ axor));
            uint32_t bh[4];
            ldsm4(bh[0], bh[1], bh[2], bh[3], bB + boff);
            const uint32_t aoff = (uint32_t)(arow0 + ((kb + akq) ^ axor));
            #pragma unroll
            for (int t = 0; t < 9; t++) {
                uint32_t ah[4];
                ldsm4(ah[0], ah[1], ah[2], ah[3], aB + aoff + t * 2048);
                mma16816(acc[t][0], ah, bh);
                mma16816(acc[t][1], ah, bh + 2);
            }
        }

        // feature compute for next chunk overlaps tensor drain
        if (c + 1 < NCHUNK) stage_A(c + 1, b ^ 1);
        asm volatile("cp.async.wait_group 0;" ::: "memory");
        __syncthreads();
    }

    // ---------------- epilogue: partial sums -> LN -> direct STG ----------
    float2* psum2 = (float2*)(smem + OFF_PSUM);   // [288][8] (sum, sumsq)
    float2* rms2  = (float2*)(smem + OFF_RMS);    // [288] (mean, rstd)

    #pragma unroll
    for (int t = 0; t < 9; t++) {
        #pragma unroll
        for (int e2 = 0; e2 < 2; e2++) {
            float s = acc[t][0][e2*2] + acc[t][0][e2*2+1]
                    + acc[t][1][e2*2] + acc[t][1][e2*2+1];
            float qq = acc[t][0][e2*2]*acc[t][0][e2*2] + acc[t][0][e2*2+1]*acc[t][0][e2*2+1]
                     + acc[t][1][e2*2]*acc[t][1][e2*2] + acc[t][1][e2*2+1]*acc[t][1][e2*2+1];
            s  += __shfl_xor_sync(0xffffffffu, s, 1, 32);
            qq += __shfl_xor_sync(0xffffffffu, qq, 1, 32);
            s  += __shfl_xor_sync(0xffffffffu, s, 2, 32);
            qq += __shfl_xor_sync(0xffffffffu, qq, 2, 32);
            if ((lid & 3) == 0) {
                int r = Mg*144 + t*16 + 8*e2 + (lid >> 2);
                psum2[r*8 + Ng] = make_float2(s, qq);
            }
        }
    }
    __syncthreads();
    for (int r = tid; r < TM; r += NTHR) {
        float s = 0.0f, qq = 0.0f;
        const float2* p = &psum2[r*8];
        #pragma unroll
        for (int g = 0; g < 8; g++) { s += p[g].x; qq += p[g].y; }
        float mean = s * (1.0f / 128.0f);
        float var  = qq * (1.0f / 128.0f) - mean * mean;
        rms2[r] = make_float2(mean, rsqrtf(var + 1e-5f));
    }
    __syncthreads();

    const int colb = Ng*16 + (lid & 3)*2;
    const float2 g0 = *(const float2*)&sgam[colb];
    const float2 g1 = *(const float2*)&sgam[colb + 8];
    const float2 b0 = *(const float2*)&sbet[colb];
    const float2 b1 = *(const float2*)&sbet[colb + 8];

    #pragma unroll
    for (int t = 0; t < 9; t++) {
        #pragma unroll
        for (int e2 = 0; e2 < 2; e2++) {
            int rl  = Mg*144 + t*16 + 8*e2 + (lid >> 2);
            int row = row0 + rl;
            if (row < nrows) {
                float2 mr = rms2[rl];
                float2 o0, o1;
                o0.x = (acc[t][0][e2*2]   - mr.x) * mr.y * g0.x + b0.x;
                o0.y = (acc[t][0][e2*2+1] - mr.x) * mr.y * g0.y + b0.y;
                o1.x = (acc[t][1][e2*2]   - mr.x) * mr.y * g1.x + b1.x;
                o1.y = (acc[t][1][e2*2+1] - mr.x) * mr.y * g1.y + b1.y;
                *(float2*)&out[(size_t)row * EC + colb]     = o0;
                *(float2*)&out[(size_t)row * EC + colb + 8] = o1;
            }
        }
    }
}

extern "C" void kernel_launch(void* const* d_in, const int* in_sizes, int n_in,
                              void* d_out, int out_size)
{
    const float* X           = (const float*)d_in[0];
    const int*   residue_idx = (const int*)  d_in[1];
    const int*   chain_lab   = (const int*)  d_in[2];
    const int*   E_idx       = (const int*)  d_in[3];
    // d_in[4] = atom_mask (unused by reference)
    const float* W_pos       = (const float*)d_in[5];
    const float* b_pos       = (const float*)d_in[6];
    const float* W_edge      = (const float*)d_in[7];
    const float* ln_gamma    = (const float*)d_in[8];
    const float* ln_beta     = (const float*)d_in[9];
    float*       out         = (float*)d_out;

    const int BL    = in_sizes[1];
    const int nrows = in_sizes[3];
    const int Kn    = nrows / BL;
    const int A     = in_sizes[0] / (BL * 3);
    const int write_eidx = (out_size >= nrows * (EC + 1)) ? 1 : 0;

    prepack_kernel<<<(NCHUNK*KC*EC + 255) / 256, 256>>>(W_edge);

    const int grid = (nrows + TM - 1) / TM;
    cudaFuncSetAttribute(spf_kernel,
                         cudaFuncAttributeMaxDynamicSharedMemorySize, SMEM_TOTAL);
    spf_kernel<<<grid, NTHR, SMEM_TOTAL>>>(X, residue_idx, chain_lab, E_idx,
                                           W_pos, b_pos, ln_gamma, ln_beta,
                                           out, Kn, A, nrows, write_eidx);
}

// round 17
// speedup vs baseline: 1.0402x; 1.0402x over previous
#include <cuda_runtime.h>
#include <cuda_fp16.h>
#include <cstdint>

#define TM     144
#define KC     64
#define NCHUNK 11
#define EC     128
#define NF     656
#define NTHR   256

// smem byte offsets
#define ABUF   18432          // 144 x 64 fp16 per buffer
#define OFF_A     0           // 2 x 18432
#define OFF_B     36864       // 2 x 16384
#define OFF_DIST  69632       // 144*41*4 = 23616
#define OFF_SMUL  93248       // 576
#define OFF_DPOS  93824       // 576
#define OFF_GAM   94400       // 512
#define OFF_BET   94912       // 512
#define SMEM_TOTAL 95424
// epilogue reuse of A region:
#define OFF_PSUM  0           // 144*8 float2 = 9216
#define OFF_RMS   10240       // 144 float2 = 1152

// Prepacked W: fp16, [chunk][n][kk] K-major rows of 128B, SW128-swizzled
__device__ __align__(128) __half g_B[NCHUNK * KC * EC];

__device__ __forceinline__ uint32_t smem_u32(const void* p) {
    return (uint32_t)__cvta_generic_to_shared(p);
}
__device__ __forceinline__ void cp_async16(uint32_t dst, const void* src) {
    asm volatile("cp.async.cg.shared.global [%0], [%1], 16;"
                 :: "r"(dst), "l"(src) : "memory");
}
__device__ __forceinline__ void ldsm4(uint32_t& r0, uint32_t& r1,
                                      uint32_t& r2, uint32_t& r3, uint32_t addr) {
    asm volatile("ldmatrix.sync.aligned.m8n8.x4.shared.b16 {%0,%1,%2,%3}, [%4];"
                 : "=r"(r0), "=r"(r1), "=r"(r2), "=r"(r3) : "r"(addr));
}
__device__ __forceinline__ void mma16816(float* d, const uint32_t* a, const uint32_t* b) {
    asm volatile("mma.sync.aligned.m16n8k16.row.col.f32.f16.f16.f32 "
        "{%0,%1,%2,%3}, {%4,%5,%6,%7}, {%8,%9}, {%0,%1,%2,%3};"
        : "+f"(d[0]), "+f"(d[1]), "+f"(d[2]), "+f"(d[3])
        : "r"(a[0]), "r"(a[1]), "r"(a[2]), "r"(a[3]), "r"(b[0]), "r"(b[1]));
}
__device__ __forceinline__ uint32_t sw128(uint32_t off) {
    return off ^ ((off >> 3) & 0x70);
}

// ---- prepack: W_edge -> fp16, swizzled, chunk-contiguous -----------------
__global__ void prepack_kernel(const float* __restrict__ W_edge) {
    int idx = blockIdx.x * 256 + threadIdx.x;
    if (idx >= NCHUNK * KC * EC) return;
    int c   = idx / (KC * EC);
    int rem = idx % (KC * EC);
    int kk  = rem / EC;
    int n   = rem % EC;
    int k   = c * KC + kk;
    float v = (k < NF) ? W_edge[(size_t)k * EC + n] : 0.0f;
    uint32_t off = sw128((uint32_t)(n * 128 + kk * 2));
    *(__half*)((char*)g_B + (size_t)c * 16384 + off) = __float2half(v);
}

// ---- main kernel --------------------------------------------------------
__global__ __launch_bounds__(NTHR, 2)
void spf_kernel(const float* __restrict__ X,
                const int*   __restrict__ residue_idx,
                const int*   __restrict__ chain_labels,
                const int*   __restrict__ E_idx,
                const float* __restrict__ W_pos,
                const float* __restrict__ b_pos,
                const float* __restrict__ ln_gamma,
                const float* __restrict__ ln_beta,
                float*       __restrict__ out,
                int Kn, int A, int nrows, int write_eidx)
{
    extern __shared__ char smem[];
    const uint32_t sb = smem_u32(smem);
    float* dist  = (float*)(smem + OFF_DIST);
    float* smul  = (float*)(smem + OFF_SMUL);
    int*   dposs = (int*)  (smem + OFF_DPOS);
    float* sgam  = (float*)(smem + OFF_GAM);
    float* sbet  = (float*)(smem + OFF_BET);

    const int tid  = threadIdx.x;
    const int wid  = tid >> 5;
    const int lid  = tid & 31;
    const int row0 = blockIdx.x * TM;

    // staging helpers ------------------------------------------------------
    auto stage_B = [&](int c, int b) {
        const char* src = (const char*)g_B + (size_t)c * 16384;
        const uint32_t d = sb + OFF_B + b * 16384;
        #pragma unroll
        for (int i = 0; i < 4; i++) {
            int g = tid + i * NTHR;          // 0..1023
            cp_async16(d + g*16, src + g*16);
        }
        asm volatile("cp.async.commit_group;" ::: "memory");
    };

    auto stage_A = [&](int c, int b) {
        char* ab = smem + OFF_A + b * ABUF;
        #pragma unroll
        for (int it = 0; it < 3; it++) {
            const int id = tid + it * NTHR;
            if (id >= 4 * TM) break;
            const int r    = id % TM;
            const int gsub = id / TM;        // 0..3
            const int gl   = c * 4 + gsub;   // global 16-k group
            float vals[16];
            if (gl == 0) {
                const int dp = dposs[r];
                #pragma unroll
                for (int m = 0; m < 16; m++)
                    vals[m] = W_pos[dp*16 + m] + b_pos[m];
            } else if (gl <= 40) {
                const float d  = dist[r*41 + (gl - 1)];
                const float sm = smul[r];
                #pragma unroll
                for (int m = 0; m < 16; m++) {
                    float mu = 2.0f + (float)m * (20.0f / 15.0f);
                    float t  = (d - mu) * 0.8f;
                    vals[m]  = sm * __expf(-t * t);
                }
            } else {
                #pragma unroll
                for (int m = 0; m < 16; m++) vals[m] = 0.0f;
            }
            uint32_t hp[8];
            #pragma unroll
            for (int i = 0; i < 8; i++) {
                __half2 h2 = __floats2half2_rn(vals[2*i], vals[2*i+1]);
                hp[i] = *(uint32_t*)&h2;
            }
            uint32_t base = (uint32_t)(r * 128 + gsub * 32);
            uint32_t s0 = sw128(base), s1 = sw128(base + 16);
            *(uint4*)(ab + s0) = make_uint4(hp[0], hp[1], hp[2], hp[3]);
            *(uint4*)(ab + s1) = make_uint4(hp[4], hp[5], hp[6], hp[7]);
        }
    };

    // kick B chunk-0 staging immediately (independent of phase 1)
    stage_B(0, 0);

    // ---------------- Phase 1: distances, smul, dpos, gamma/beta ----------
    for (int task = tid; task < 2 * TM; task += NTHR) {
        const int r    = task >> 1;
        const int half = task & 1;           // bb atoms {0,1} or {2,3}
        const int row  = row0 + r;
        if (row < nrows) {
            const int i = row / Kn;
            const int j = E_idx[row];
            const int bbm[4] = {1, 0, 2, 3};
            const float* sx = X + ((size_t)j * A + 4) * 3;
            float s[30];
            #pragma unroll
            for (int q = 0; q < 30; q++) s[q] = sx[q];
            #pragma unroll
            for (int aa = 0; aa < 2; aa++) {
                const int a1 = half*2 + aa;
                const float* bx = X + ((size_t)i * A + bbm[a1]) * 3;
                const float b0 = bx[0], b1 = bx[1], b2 = bx[2];
                #pragma unroll
                for (int a2 = 0; a2 < 10; a2++) {
                    float dx = b0 - s[a2*3+0];
                    float dy = b1 - s[a2*3+1];
                    float dz = b2 - s[a2*3+2];
                    dist[r*41 + a1*10 + a2] = sqrtf(dx*dx + dy*dy + dz*dz + 1e-6f);
                }
            }
            if (half == 0) {
                smul[r] = (j == i) ? 0.0f : 1.0f;
                int off  = residue_idx[i] - residue_idx[j];
                int same = (chain_labels[i] == chain_labels[j]);
                dposs[r] = same ? min(max(off + 32, 0), 64) : 65;
                if (write_eidx)
                    out[(size_t)nrows * EC + row] = (float)j;
            }
        } else {
            #pragma unroll
            for (int aa = 0; aa < 2; aa++)
                #pragma unroll
                for (int a2 = 0; a2 < 10; a2++)
                    dist[r*41 + (half*2+aa)*10 + a2] = 0.0f;
            if (half == 0) { smul[r] = 0.0f; dposs[r] = 0; }
        }
    }
    if (tid < 128)      sgam[tid]       = ln_gamma[tid];
    else if (tid < 256) sbet[tid - 128] = ln_beta[tid - 128];
    __syncthreads();

    // prologue: features for chunk 0
    stage_A(0, 0);
    asm volatile("cp.async.wait_group 0;" ::: "memory");
    __syncthreads();

    // ---------------- Phase 2: MMA mainloop (single-pass fp16) ------------
    // 8 warps, all N-split: warp = 144 rows (9 m16) x 16 cols (1 n16)
    const int q  = lid >> 3;
    const int lr = lid & 7;
    const int axor  = lr << 4;
    const int arow0 = (lr + (q & 1) * 8) * 128;            // + t*2048 per m16
    const int brow0 = (wid*16 + lr + (q >> 1) * 8) * 128;
    const int akq = (q >> 1) * 16;
    const int bkq = (q & 1) * 16;

    float acc[9][2][4];
    #pragma unroll
    for (int t = 0; t < 9; t++)
        #pragma unroll
        for (int j = 0; j < 2; j++)
            #pragma unroll
            for (int e = 0; e < 4; e++) acc[t][j][e] = 0.0f;

    for (int c = 0; c < NCHUNK; c++) {
        const int b = c & 1;
        // issue next-chunk B loads first so global latency hides under MMA
        if (c + 1 < NCHUNK) stage_B(c + 1, b ^ 1);

        const uint32_t aB = sb + OFF_A + b * ABUF;
        const uint32_t bB = sb + OFF_B + b * 16384;

        #pragma unroll
        for (int ks = 0; ks < 4; ks++) {
            const int kb = ks * 32;
            const uint32_t boff = (uint32_t)(brow0 + ((kb + bkq) ^ axor));
            uint32_t bh[4];
            ldsm4(bh[0], bh[1], bh[2], bh[3], bB + boff);
            const uint32_t aoff = (uint32_t)(arow0 + ((kb + akq) ^ axor));
            #pragma unroll
            for (int t = 0; t < 9; t++) {
                uint32_t ah[4];
                ldsm4(ah[0], ah[1], ah[2], ah[3], aB + aoff + t * 2048);
                mma16816(acc[t][0], ah, bh);
                mma16816(acc[t][1], ah, bh + 2);
            }
        }

        // feature compute for next chunk overlaps tensor drain
        if (c + 1 < NCHUNK) stage_A(c + 1, b ^ 1);
        asm volatile("cp.async.wait_group 0;" ::: "memory");
        __syncthreads();
    }

    // ---------------- epilogue: partial sums -> LN -> direct STG ----------
    float2* psum2 = (float2*)(smem + OFF_PSUM);   // [144][8] (sum, sumsq)
    float2* rms2  = (float2*)(smem + OFF_RMS);    // [144] (mean, rstd)

    #pragma unroll
    for (int t = 0; t < 9; t++) {
        #pragma unroll
        for (int e2 = 0; e2 < 2; e2++) {
            float s = acc[t][0][e2*2] + acc[t][0][e2*2+1]
                    + acc[t][1][e2*2] + acc[t][1][e2*2+1];
            float qq = acc[t][0][e2*2]*acc[t][0][e2*2] + acc[t][0][e2*2+1]*acc[t][0][e2*2+1]
                     + acc[t][1][e2*2]*acc[t][1][e2*2] + acc[t][1][e2*2+1]*acc[t][1][e2*2+1];
            s  += __shfl_xor_sync(0xffffffffu, s, 1, 32);
            qq += __shfl_xor_sync(0xffffffffu, qq, 1, 32);
            s  += __shfl_xor_sync(0xffffffffu, s, 2, 32);
            qq += __shfl_xor_sync(0xffffffffu, qq, 2, 32);
            if ((lid & 3) == 0) {
                int r = t*16 + 8*e2 + (lid >> 2);
                psum2[r*8 + wid] = make_float2(s, qq);
            }
        }
    }
    __syncthreads();
    for (int r = tid; r < TM; r += NTHR) {
        float s = 0.0f, qq = 0.0f;
        const float2* p = &psum2[r*8];
        #pragma unroll
        for (int g = 0; g < 8; g++) { s += p[g].x; qq += p[g].y; }
        float mean = s * (1.0f / 128.0f);
        float var  = qq * (1.0f / 128.0f) - mean * mean;
        rms2[r] = make_float2(mean, rsqrtf(var + 1e-5f));
    }
    __syncthreads();

    const int colb = wid*16 + (lid & 3)*2;
    const float2 g0 = *(const float2*)&sgam[colb];
    const float2 g1 = *(const float2*)&sgam[colb + 8];
    const float2 b0 = *(const float2*)&sbet[colb];
    const float2 b1 = *(const float2*)&sbet[colb + 8];

    #pragma unroll
    for (int t = 0; t < 9; t++) {
        #pragma unroll
        for (int e2 = 0; e2 < 2; e2++) {
            int rl  = t*16 + 8*e2 + (lid >> 2);
            int row = row0 + rl;
            if (row < nrows) {
                float2 mr = rms2[rl];
                float2 o0, o1;
                o0.x = (acc[t][0][e2*2]   - mr.x) * mr.y * g0.x + b0.x;
                o0.y = (acc[t][0][e2*2+1] - mr.x) * mr.y * g0.y + b0.y;
                o1.x = (acc[t][1][e2*2]   - mr.x) * mr.y * g1.x + b1.x;
                o1.y = (acc[t][1][e2*2+1] - mr.x) * mr.y * g1.y + b1.y;
                *(float2*)&out[(size_t)row * EC + colb]     = o0;
                *(float2*)&out[(size_t)row * EC + colb + 8] = o1;
            }
        }
    }
}

extern "C" void kernel_launch(void* const* d_in, const int* in_sizes, int n_in,
                              void* d_out, int out_size)
{
    const float* X           = (const float*)d_in[0];
    const int*   residue_idx = (const int*)  d_in[1];
    const int*   chain_lab   = (const int*)  d_in[2];
    const int*   E_idx       = (const int*)  d_in[3];
    // d_in[4] = atom_mask (unused by reference)
    const float* W_pos       = (const float*)d_in[5];
    const float* b_pos       = (const float*)d_in[6];
    const float* W_edge      = (const float*)d_in[7];
    const float* ln_gamma    = (const float*)d_in[8];
    const float* ln_beta     = (const float*)d_in[9];
    float*       out         = (float*)d_out;

    const int BL    = in_sizes[1];
    const int nrows = in_sizes[3];
    const int Kn    = nrows / BL;
    const int A     = in_sizes[0] / (BL * 3);
    const int write_eidx = (out_size >= nrows * (EC + 1)) ? 1 : 0;

    prepack_kernel<<<(NCHUNK*KC*EC + 255) / 256, 256>>>(W_edge);

    const int grid = (nrows + TM - 1) / TM;
    cudaFuncSetAttribute(spf_kernel,
                         cudaFuncAttributeMaxDynamicSharedMemorySize, SMEM_TOTAL);
    spf_kernel<<<grid, NTHR, SMEM_TOTAL>>>(X, residue_idx, chain_lab, E_idx,
                                           W_pos, b_pos, ln_gamma, ln_beta,
                                           out, Kn, A, nrows, write_eidx);
}